// round 7
// baseline (speedup 1.0000x reference)
#include <cuda_runtime.h>
#include <cuda_fp16.h>
#include <cstdint>
#include <cstddef>

#define BATCH 128
#define T     128
#define NF    128
#define M     256
#define TWO_M 512
#define KDIM  384      // NF + M
#define G4M   1024     // 4*M
#define THREADS 512

typedef unsigned long long u64;

// ------------- device scratch (fixed globals; no runtime allocation) -------------
__device__ __align__(16) __half g_W[G4M * KDIM];     // [row][k] = [W_ih | W_hh], fp16
__device__ __align__(16) __half g_WeS[T * TWO_M];    // = We, fp16, row-major [s][k]
__device__ float                g_bias[G4M];         // b_ih + b_hh
__device__ __align__(16) float  g_Ux[BATCH * T * NF];// [b][s][n] fp32

// ------------- helpers -------------
__device__ __forceinline__ u64 ffma2(u64 a, u64 b, u64 c) {
    u64 d;
    asm("fma.rn.f32x2 %0, %1, %2, %3;" : "=l"(d) : "l"(a), "l"(b), "l"(c));
    return d;
}
__device__ __forceinline__ u64 h2u(__half2 h) {
    float2 f = __half22float2(h);
    u64 r;
    asm("mov.b64 %0, {%1, %2};" : "=l"(r) : "f"(f.x), "f"(f.y));
    return r;
}
__device__ __forceinline__ float usum(u64 v) {
    float lo, hi;
    asm("mov.b64 {%0, %1}, %2;" : "=f"(lo), "=f"(hi) : "l"(v));
    return lo + hi;
}
__device__ __forceinline__ float tanh_acc(float x) {
    x = fminf(fmaxf(x, -15.f), 15.f);
    float e = __expf(2.f * x);
    return __fdividef(e - 1.f, e + 1.f);
}
__device__ __forceinline__ float sigm(float x) {
    return __fdividef(1.f, 1.f + __expf(-x));
}

// ------------- prep: pack weights -------------
__global__ void __launch_bounds__(256) prep_w_kernel(
        const float* __restrict__ W_ih, const float* __restrict__ W_hh,
        const float* __restrict__ b_ih, const float* __restrict__ b_hh,
        const float* __restrict__ We) {
    int idx = blockIdx.x * blockDim.x + threadIdx.x;
    int stride = gridDim.x * blockDim.x;
    for (int i = idx; i < G4M * KDIM; i += stride) {
        int r = i / KDIM;
        int k = i - r * KDIM;
        float v = (k < NF) ? W_ih[r * NF + k] : W_hh[r * M + (k - NF)];
        g_W[i] = __float2half(v);
    }
    for (int i = idx; i < T * TWO_M; i += stride)
        g_WeS[i] = __float2half(We[i]);
    for (int i = idx; i < G4M; i += stride)
        g_bias[i] = b_ih[i] + b_hh[i];
}

// ------------- prep: Ux[b,s,n] = sum_t x[b,t,n] * Ue[s,t] -------------
__global__ void __launch_bounds__(256) prep_ux_kernel(
        const float* __restrict__ x, const float* __restrict__ Ue) {
    extern __shared__ float sm_u[];
    float* xs = sm_u;            // [T][NF]
    float* ue = sm_u + T * NF;   // [s][t]
    int b = blockIdx.x;
    int tid = threadIdx.x;
    for (int i = tid; i < T * NF; i += 256) xs[i] = x[(size_t)b * T * NF + i];
    for (int i = tid; i < T * T;  i += 256) ue[i] = Ue[i];
    __syncthreads();

    int n  = tid & (NF - 1);
    int sb = tid >> 7;  // 0..1
    for (int j8 = 0; j8 < 8; j8++) {
        int s0 = sb * 64 + j8 * 8;
        float acc[8];
        #pragma unroll
        for (int u = 0; u < 8; u++) acc[u] = 0.f;
        for (int tt = 0; tt < T; tt++) {
            float xv = xs[tt * NF + n];
            #pragma unroll
            for (int u = 0; u < 8; u++)
                acc[u] = fmaf(xv, ue[(s0 + u) * T + tt], acc[u]);
        }
        #pragma unroll
        for (int u = 0; u < 8; u++)
            g_Ux[(size_t)b * T * NF + (s0 + u) * NF + n] = acc[u];
    }
}

// ------------- main persistent kernel: one CTA per batch -------------
// SMEM byte layout:
//   [0, 131072)        s_We   : 128x512 half (= We fp16)
//   [131072, 196608)   s_Ux   : 128x128 float
//   [196608, 200704)   s_bias : 1024 float
//   [200704, 212000)   float scratch:
//       hs[512] part[512] a_s[128] scb[128] ve[128] act[384] gates[1024] red[8]
#define OFF_UX   131072
#define OFF_BIAS 196608
#define OFF_F    200704
#define SMEM_MAIN 212000

__global__ void __launch_bounds__(THREADS, 1) main_kernel(
        const float* __restrict__ x, const float* __restrict__ ve_g,
        float* __restrict__ out) {
    extern __shared__ char smraw[];
    __half* s_We   = (__half*)smraw;
    float*  s_Ux   = (float*)(smraw + OFF_UX);
    float*  s_bias = (float*)(smraw + OFF_BIAS);
    float*  F      = (float*)(smraw + OFF_F);
    float* hs    = F;            // [512] = [h | c]
    float* part  = F + 512;      // [4][128]
    float* a_s   = F + 1024;     // [128]
    float* scb   = F + 1152;     // [128]
    float* ve_s  = F + 1280;     // [128]
    float* act   = F + 1408;     // [384] = [xw | h]
    float* gates = F + 1792;     // [1024]
    float* red   = F + 2816;     // [8]

    const int tid = threadIdx.x;
    const int b   = blockIdx.x;

    // ---- one-time staging ----
    {
        uint4* d = (uint4*)s_We;
        const uint4* s = (const uint4*)g_WeS;
        for (int i = tid; i < (T * TWO_M * 2) / 16; i += THREADS) d[i] = s[i];
        uint4* d2 = (uint4*)s_Ux;
        const uint4* s2 = (const uint4*)(g_Ux + (size_t)b * T * NF);
        for (int i = tid; i < (T * NF * 4) / 16; i += THREADS) d2[i] = s2[i];
        for (int i = tid; i < G4M; i += THREADS) s_bias[i] = g_bias[i];
        if (tid < TWO_M) hs[tid] = 0.f;
        if (tid < T) ve_s[tid] = ve_g[tid];
    }
    __syncthreads();

    const int q  = tid >> 7;    // k/s-quarter
    const int sn = tid & 127;   // s (phase A) / n (phase B)

    for (int t = 0; t < T; t++) {
        // ---- Phase A: a[s] = sum_k hs[k] * We[s][k]  (k split 4 ways) ----
        {
            const uint4* wr = ((const uint4*)s_We) + sn * 64 + q * 16;
            const u64*   hq = ((const u64*)hs) + q * 64;
            u64 acc = 0ULL;
            #pragma unroll
            for (int c = 0; c < 16; c++) {
                uint4 w = wr[c];
                const __half2* hp = (const __half2*)&w;
                acc = ffma2(h2u(hp[0]), hq[4 * c + 0], acc);
                acc = ffma2(h2u(hp[1]), hq[4 * c + 1], acc);
                acc = ffma2(h2u(hp[2]), hq[4 * c + 2], acc);
                acc = ffma2(h2u(hp[3]), hq[4 * c + 3], acc);
            }
            part[q * 128 + sn] = usum(acc);
        }
        __syncthreads();
        if (tid < 128)
            a_s[tid] = part[tid] + part[128 + tid] + part[256 + tid] + part[384 + tid];
        __syncthreads();

        // ---- Phase B: scores[n] partials over s-quarter ----
        {
            float acc = 0.f;
            const int sbase = q * 32;
            #pragma unroll 8
            for (int i = 0; i < 32; i++) {
                int ss = sbase + i;
                float zv = a_s[ss] + s_Ux[ss * NF + sn];
                acc = fmaf(ve_s[ss], tanh_acc(zv), acc);
            }
            part[q * 128 + sn] = acc;
        }
        __syncthreads();

        // ---- reduce + softmax stats (warp 0); copy h into act (other threads) ----
        if (tid < 32) {
            float v0 = 0.f, v1 = 0.f, v2 = 0.f, v3 = 0.f;
            #pragma unroll
            for (int qq = 0; qq < 4; qq++) {
                v0 += part[qq * 128 + tid];
                v1 += part[qq * 128 + tid + 32];
                v2 += part[qq * 128 + tid + 64];
                v3 += part[qq * 128 + tid + 96];
            }
            scb[tid] = v0; scb[tid + 32] = v1; scb[tid + 64] = v2; scb[tid + 96] = v3;
            float mx = fmaxf(fmaxf(v0, v1), fmaxf(v2, v3));
            #pragma unroll
            for (int o = 16; o; o >>= 1) mx = fmaxf(mx, __shfl_xor_sync(0xffffffffu, mx, o));
            float sum = __expf(v0 - mx) + __expf(v1 - mx) + __expf(v2 - mx) + __expf(v3 - mx);
            #pragma unroll
            for (int o = 16; o; o >>= 1) sum += __shfl_xor_sync(0xffffffffu, sum, o);
            if (tid == 0) { red[0] = mx; red[1] = __fdividef(1.f, sum); }
        }
        if (tid >= 128 && tid < 384)
            act[NF + (tid - 128)] = hs[tid - 128];
        __syncthreads();

        // ---- Phase C: act[0:128] = x_t * alpha ----
        if (tid < 128) {
            float al = __expf(scb[tid] - red[0]) * red[1];
            act[tid] = x[((size_t)b * T + t) * NF + tid] * al;
        }
        __syncthreads();

        // ---- Phase D: gates[r] = act . W[r] + bias[r]  (rows tid, tid+512) ----
        {
            const int r0 = tid, r1 = tid + 512;
            const uint4* w0 = ((const uint4*)g_W) + (size_t)r0 * 48;
            const uint4* w1 = ((const uint4*)g_W) + (size_t)r1 * 48;
            const u64*   au = (const u64*)act;
            u64 acc0 = 0ULL, acc1 = 0ULL;
            #pragma unroll 8
            for (int c = 0; c < 48; c++) {
                uint4 wa = w0[c];
                uint4 wb = w1[c];
                u64 a0 = au[4 * c + 0];
                u64 a1 = au[4 * c + 1];
                u64 a2 = au[4 * c + 2];
                u64 a3 = au[4 * c + 3];
                const __half2* ha = (const __half2*)&wa;
                const __half2* hb = (const __half2*)&wb;
                acc0 = ffma2(h2u(ha[0]), a0, acc0);
                acc0 = ffma2(h2u(ha[1]), a1, acc0);
                acc0 = ffma2(h2u(ha[2]), a2, acc0);
                acc0 = ffma2(h2u(ha[3]), a3, acc0);
                acc1 = ffma2(h2u(hb[0]), a0, acc1);
                acc1 = ffma2(h2u(hb[1]), a1, acc1);
                acc1 = ffma2(h2u(hb[2]), a2, acc1);
                acc1 = ffma2(h2u(hb[3]), a3, acc1);
            }
            gates[r0] = usum(acc0) + s_bias[r0];
            gates[r1] = usum(acc1) + s_bias[r1];
        }
        __syncthreads();

        // ---- LSTM cell update (i, f, g, o) ----
        if (tid < M) {
            float iv = gates[tid];
            float fv = gates[M + tid];
            float gv = gates[2 * M + tid];
            float ov = gates[3 * M + tid];
            float c_old = hs[M + tid];
            float c2 = sigm(fv) * c_old + sigm(iv) * tanh_acc(gv);
            float h2v = sigm(ov) * tanh_acc(c2);
            hs[tid] = h2v;
            hs[M + tid] = c2;
            out[((size_t)t * BATCH + b) * M + tid] = h2v;
        }
        __syncthreads();
    }
}

extern "C" void kernel_launch(void* const* d_in, const int* in_sizes, int n_in,
                              void* d_out, int out_size) {
    const float* x    = (const float*)d_in[0];
    const float* We   = (const float*)d_in[1];
    const float* Ue   = (const float*)d_in[2];
    const float* v_e  = (const float*)d_in[3];
    const float* W_ih = (const float*)d_in[4];
    const float* W_hh = (const float*)d_in[5];
    const float* b_ih = (const float*)d_in[6];
    const float* b_hh = (const float*)d_in[7];
    float* out = (float*)d_out;
    (void)in_sizes; (void)n_in; (void)out_size;

    cudaFuncSetAttribute(prep_ux_kernel, cudaFuncAttributeMaxDynamicSharedMemorySize, 131072);
    cudaFuncSetAttribute(main_kernel,    cudaFuncAttributeMaxDynamicSharedMemorySize, SMEM_MAIN);

    prep_w_kernel<<<256, 256>>>(W_ih, W_hh, b_ih, b_hh, We);
    prep_ux_kernel<<<BATCH, 256, 131072>>>(x, Ue);
    main_kernel<<<BATCH, THREADS, SMEM_MAIN>>>(x, v_e, out);
}

// round 11
// speedup vs baseline: 4.2432x; 4.2432x over previous
#include <cuda_runtime.h>
#include <cuda_fp16.h>
#include <cstdint>
#include <cstddef>

#define BATCH 128
#define T     128
#define NF    128
#define M     256
#define TWO_M 512
#define KDIM  384      // NF + M
#define G4M   1024     // 4*M
#define KB    2        // batches per CTA
#define CTAS  (BATCH / KB)
#define THREADS 512

typedef unsigned long long u64;

// ------------- device scratch (fixed globals; no runtime allocation) -------------
// Swizzled gate weights: g_Wp[kc][row][8] halves, kc = k/8 (48 groups), row 0..1023
__device__ __align__(16) __half g_Wp[48 * G4M * 8];
// Swizzled We: g_WeT[kc][s][8] halves, kc = k/8 (64 groups), s 0..127
__device__ __align__(16) __half g_WeT[64 * T * 8];
__device__ float                g_bias[G4M];            // b_ih + b_hh
__device__ __align__(16) __half g_Uxh[BATCH * T * NF];  // [b][s][n] fp16

// ------------- helpers -------------
__device__ __forceinline__ u64 ffma2(u64 a, u64 b, u64 c) {
    u64 d;
    asm("fma.rn.f32x2 %0, %1, %2, %3;" : "=l"(d) : "l"(a), "l"(b), "l"(c));
    return d;
}
__device__ __forceinline__ u64 h2u(__half2 h) {
    float2 f = __half22float2(h);
    u64 r;
    asm("mov.b64 %0, {%1, %2};" : "=l"(r) : "f"(f.x), "f"(f.y));
    return r;
}
__device__ __forceinline__ float usum(u64 v) {
    float lo, hi;
    asm("mov.b64 {%0, %1}, %2;" : "=f"(lo), "=f"(hi) : "l"(v));
    return lo + hi;
}
__device__ __forceinline__ float tanh_fast(float x) {   // score path only
    float y;
    asm("tanh.approx.f32 %0, %1;" : "=f"(y) : "f"(x));
    return y;
}
__device__ __forceinline__ float tanh_acc(float x) {    // cell path (accurate)
    x = fminf(fmaxf(x, -15.f), 15.f);
    float e = __expf(2.f * x);
    return __fdividef(e - 1.f, e + 1.f);
}
__device__ __forceinline__ float sigm(float x) {
    return __fdividef(1.f, 1.f + __expf(-x));
}

// ------------- prep: pack + swizzle weights -------------
__global__ void __launch_bounds__(256) prep_w_kernel(
        const float* __restrict__ W_ih, const float* __restrict__ W_hh,
        const float* __restrict__ b_ih, const float* __restrict__ b_hh,
        const float* __restrict__ We) {
    int idx = blockIdx.x * blockDim.x + threadIdx.x;
    int stride = gridDim.x * blockDim.x;
    // g_Wp[kc][r][kl]  <- W[r][kc*8+kl]
    for (int o = idx; o < 48 * G4M * 8; o += stride) {
        int kc  = o >> 13;          // / (1024*8)
        int rem = o & 8191;
        int r   = rem >> 3;
        int kl  = rem & 7;
        int k   = kc * 8 + kl;
        float v = (k < NF) ? W_ih[r * NF + k] : W_hh[r * M + (k - NF)];
        g_Wp[o] = __float2half(v);
    }
    // g_WeT[kc][s][kl] <- We[s][kc*8+kl]
    for (int o = idx; o < 64 * T * 8; o += stride) {
        int kc  = o >> 10;          // / (128*8)
        int rem = o & 1023;
        int s   = rem >> 3;
        int kl  = rem & 7;
        int k   = kc * 8 + kl;
        g_WeT[o] = __float2half(We[s * TWO_M + k]);
    }
    for (int i = idx; i < G4M; i += stride)
        g_bias[i] = b_ih[i] + b_hh[i];
}

// ------------- prep: Ux[b,s,n] = sum_t x[b,t,n] * Ue[s,t]  (fp16 out) -------------
__global__ void __launch_bounds__(256) prep_ux_kernel(
        const float* __restrict__ x, const float* __restrict__ Ue) {
    extern __shared__ float sm_u[];
    float* xs = sm_u;            // [T][NF]
    float* ue = sm_u + T * NF;   // [s][t]
    int b = blockIdx.x;
    int tid = threadIdx.x;
    for (int i = tid; i < T * NF; i += 256) xs[i] = x[(size_t)b * T * NF + i];
    for (int i = tid; i < T * T;  i += 256) ue[i] = Ue[i];
    __syncthreads();

    int n  = tid & (NF - 1);
    int sb = tid >> 7;  // 0..1
    for (int j8 = 0; j8 < 8; j8++) {
        int s0 = sb * 64 + j8 * 8;
        float acc[8];
        #pragma unroll
        for (int u = 0; u < 8; u++) acc[u] = 0.f;
        for (int tt = 0; tt < T; tt++) {
            float xv = xs[tt * NF + n];
            #pragma unroll
            for (int u = 0; u < 8; u++)
                acc[u] = fmaf(xv, ue[(s0 + u) * T + tt], acc[u]);
        }
        #pragma unroll
        for (int u = 0; u < 8; u++)
            g_Uxh[(size_t)b * T * NF + (s0 + u) * NF + n] = __float2half(acc[u]);
    }
}

// ------------- main persistent kernel: 64 CTAs x 2 batches -------------
// SMEM byte layout:
//   [0, 131072)        s_We  : swizzled We_t[kc][s][8] halves (128 KB)
//   [131072, 196608)   s_Ux  : [kb][s][n] halves (64 KB)
//   [196608, 200704)   s_bias: 1024 floats
//   [200704, ...)      float scratch:
//       hs[2][512] part[2][512] a_s[2][128] scb[2][128] ve[128]
//       act[2][384] gates[2][1024] red[8]
#define OFF_UX    131072
#define OFF_BIAS  196608
#define OFF_F     200704
#define N_SCRATCH (1024 + 1024 + 256 + 256 + 128 + 768 + 2048 + 8)
#define SMEM_MAIN (OFF_F + N_SCRATCH * 4)

__global__ void __launch_bounds__(THREADS, 1) main_kernel(
        const float* __restrict__ x, const float* __restrict__ ve_g,
        float* __restrict__ out) {
    extern __shared__ char smraw[];
    __half* s_We   = (__half*)smraw;                 // [kc][s][8]
    __half* s_Ux   = (__half*)(smraw + OFF_UX);      // [kb][s][n]
    float*  s_bias = (float*)(smraw + OFF_BIAS);
    float*  F      = (float*)(smraw + OFF_F);
    float* hs    = F;            // [2][512] = [h | c] per batch
    float* part  = F + 1024;     // [2][4][128]
    float* a_s   = F + 2048;     // [2][128]
    float* scb   = F + 2304;     // [2][128]
    float* ve_s  = F + 2560;     // [128]
    float* act   = F + 2688;     // [2][384] = [xw | h]
    float* gates = F + 3456;     // [2][1024]
    float* red   = F + 5504;     // [8]

    const int tid = threadIdx.x;
    const int b0  = blockIdx.x * KB;

    // ---- one-time staging ----
    {
        uint4* d = (uint4*)s_We;
        const uint4* s = (const uint4*)g_WeT;
        for (int i = tid; i < (64 * T * 8 * 2) / 16; i += THREADS) d[i] = s[i];
        uint4* d2 = (uint4*)s_Ux;
        const uint4* s2 = (const uint4*)(g_Uxh + (size_t)b0 * T * NF);
        for (int i = tid; i < (KB * T * NF * 2) / 16; i += THREADS) d2[i] = s2[i];
        for (int i = tid; i < G4M; i += THREADS) s_bias[i] = g_bias[i];
        hs[tid] = 0.f;
        hs[512 + tid] = 0.f;
        if (tid < T) ve_s[tid] = ve_g[tid];
    }
    __syncthreads();

    const int q  = tid >> 7;    // k/s quarter 0..3
    const int sn = tid & 127;   // s (A) / n (B,C)

    for (int t = 0; t < T; t++) {
        // ---- Phase A: a[kb][s] = sum_k hs[kb][k] * We[s][k], k-quarter per thread ----
        {
            const uint4* wbase = (const uint4*)s_We;   // [kc][s] uint4
            const u64* h0 = (const u64*)hs;
            const u64* h1 = (const u64*)(hs + 512);
            u64 acc0 = 0ULL, acc1 = 0ULL;
            #pragma unroll 4
            for (int c = 0; c < 16; c++) {
                int kc = q * 16 + c;
                uint4 w = wbase[kc * 128 + sn];        // conflict-free: 16B lane stride
                const __half2* hp = (const __half2*)&w;
                u64 f0 = h2u(hp[0]), f1 = h2u(hp[1]), f2 = h2u(hp[2]), f3 = h2u(hp[3]);
                int k4 = kc * 4;
                acc0 = ffma2(f0, h0[k4 + 0], acc0);
                acc0 = ffma2(f1, h0[k4 + 1], acc0);
                acc0 = ffma2(f2, h0[k4 + 2], acc0);
                acc0 = ffma2(f3, h0[k4 + 3], acc0);
                acc1 = ffma2(f0, h1[k4 + 0], acc1);
                acc1 = ffma2(f1, h1[k4 + 1], acc1);
                acc1 = ffma2(f2, h1[k4 + 2], acc1);
                acc1 = ffma2(f3, h1[k4 + 3], acc1);
            }
            part[q * 128 + sn]       = usum(acc0);
            part[512 + q * 128 + sn] = usum(acc1);
        }
        __syncthreads();
        if (tid < 256) {
            int kb = tid >> 7, s = tid & 127;
            const float* p = part + kb * 512;
            a_s[kb * 128 + s] = p[s] + p[128 + s] + p[256 + s] + p[384 + s];
        }
        __syncthreads();

        // ---- Phase B: score partials over s-quarter ----
        {
            const __half* ux0 = s_Ux;
            const __half* ux1 = s_Ux + T * NF;
            float acc0 = 0.f, acc1 = 0.f;
            const int sbase = q * 32;
            #pragma unroll 8
            for (int i = 0; i < 32; i++) {
                int ss = sbase + i;
                float vv = ve_s[ss];
                float A0 = a_s[ss], A1 = a_s[128 + ss];
                float u0 = __half2float(ux0[ss * NF + sn]);
                float u1 = __half2float(ux1[ss * NF + sn]);
                acc0 = fmaf(vv, tanh_fast(A0 + u0), acc0);
                acc1 = fmaf(vv, tanh_fast(A1 + u1), acc1);
            }
            part[q * 128 + sn]       = acc0;
            part[512 + q * 128 + sn] = acc1;
        }
        __syncthreads();

        // ---- reduce scores + softmax stats (warps 0,1 -> kb 0,1); h copy elsewhere ----
        if (tid < 64) {
            int kb = tid >> 5, lane = tid & 31;
            const float* p = part + kb * 512;
            float v0 = p[lane]       + p[128 + lane]       + p[256 + lane]       + p[384 + lane];
            float v1 = p[lane + 32]  + p[128 + lane + 32]  + p[256 + lane + 32]  + p[384 + lane + 32];
            float v2 = p[lane + 64]  + p[128 + lane + 64]  + p[256 + lane + 64]  + p[384 + lane + 64];
            float v3 = p[lane + 96]  + p[128 + lane + 96]  + p[256 + lane + 96]  + p[384 + lane + 96];
            float* sc = scb + kb * 128;
            sc[lane] = v0; sc[lane + 32] = v1; sc[lane + 64] = v2; sc[lane + 96] = v3;
            float mx = fmaxf(fmaxf(v0, v1), fmaxf(v2, v3));
            #pragma unroll
            for (int o = 16; o; o >>= 1) mx = fmaxf(mx, __shfl_xor_sync(0xffffffffu, mx, o));
            float sum = __expf(v0 - mx) + __expf(v1 - mx) + __expf(v2 - mx) + __expf(v3 - mx);
            #pragma unroll
            for (int o = 16; o; o >>= 1) sum += __shfl_xor_sync(0xffffffffu, sum, o);
            if (lane == 0) { red[kb * 2] = mx; red[kb * 2 + 1] = __fdividef(1.f, sum); }
        }
        {   // act[kb][NF + j] = h[kb][j]  (all 512 threads, 2*256 entries)
            int kb2 = tid >> 8, j = tid & 255;
            act[kb2 * KDIM + NF + j] = hs[kb2 * 512 + j];
        }
        __syncthreads();

        // ---- Phase C: act[kb][0:128] = x_t * alpha ----
        if (tid < 256) {
            int kb = tid >> 7, n = tid & 127;
            float al = __expf(scb[kb * 128 + n] - red[kb * 2]) * red[kb * 2 + 1];
            float xv = x[((size_t)(b0 + kb) * T + t) * NF + n];
            act[kb * KDIM + n] = xv * al;
        }
        __syncthreads();

        // ---- Phase D: gates, rows {tid, tid+512} x both batches; coalesced W ----
        {
            const uint4* wp = (const uint4*)g_Wp;   // [kc][1024] uint4 (contiguous rows!)
            const u64* a0 = (const u64*)act;
            const u64* a1 = (const u64*)(act + KDIM);
            u64 A00 = 0ULL, A01 = 0ULL, A10 = 0ULL, A11 = 0ULL;
            #pragma unroll 4
            for (int kc = 0; kc < 48; kc++) {
                uint4 w0 = wp[kc * 1024 + tid];
                uint4 w1 = wp[kc * 1024 + tid + 512];
                const __half2* ha = (const __half2*)&w0;
                const __half2* hb = (const __half2*)&w1;
                u64 g0 = h2u(ha[0]), g1 = h2u(ha[1]), g2 = h2u(ha[2]), g3 = h2u(ha[3]);
                u64 k0 = h2u(hb[0]), k1 = h2u(hb[1]), k2 = h2u(hb[2]), k3 = h2u(hb[3]);
                u64 x0 = a0[kc * 4 + 0], x1 = a0[kc * 4 + 1];
                u64 x2 = a0[kc * 4 + 2], x3 = a0[kc * 4 + 3];
                u64 y0 = a1[kc * 4 + 0], y1 = a1[kc * 4 + 1];
                u64 y2 = a1[kc * 4 + 2], y3 = a1[kc * 4 + 3];
                A00 = ffma2(g0, x0, A00); A00 = ffma2(g1, x1, A00);
                A00 = ffma2(g2, x2, A00); A00 = ffma2(g3, x3, A00);
                A01 = ffma2(g0, y0, A01); A01 = ffma2(g1, y1, A01);
                A01 = ffma2(g2, y2, A01); A01 = ffma2(g3, y3, A01);
                A10 = ffma2(k0, x0, A10); A10 = ffma2(k1, x1, A10);
                A10 = ffma2(k2, x2, A10); A10 = ffma2(k3, x3, A10);
                A11 = ffma2(k0, y0, A11); A11 = ffma2(k1, y1, A11);
                A11 = ffma2(k2, y2, A11); A11 = ffma2(k3, y3, A11);
            }
            gates[tid]              = usum(A00) + s_bias[tid];
            gates[tid + 512]        = usum(A10) + s_bias[tid + 512];
            gates[1024 + tid]       = usum(A01) + s_bias[tid];
            gates[1024 + tid + 512] = usum(A11) + s_bias[tid + 512];
        }
        __syncthreads();

        // ---- LSTM cell update: 2 batches x 256 units = 512 threads ----
        {
            int kb = tid >> 8, u = tid & 255;
            const float* gg = gates + kb * 1024;
            float iv = gg[u];
            float fv = gg[256 + u];
            float gv = gg[512 + u];
            float ov = gg[768 + u];
            float c_old = hs[kb * 512 + 256 + u];
            float c2  = sigm(fv) * c_old + sigm(iv) * tanh_acc(gv);
            float h2v = sigm(ov) * tanh_acc(c2);
            hs[kb * 512 + u]       = h2v;
            hs[kb * 512 + 256 + u] = c2;
            out[((size_t)t * BATCH + (b0 + kb)) * M + u] = h2v;
        }
        __syncthreads();
    }
}

extern "C" void kernel_launch(void* const* d_in, const int* in_sizes, int n_in,
                              void* d_out, int out_size) {
    const float* x    = (const float*)d_in[0];
    const float* We   = (const float*)d_in[1];
    const float* Ue   = (const float*)d_in[2];
    const float* v_e  = (const float*)d_in[3];
    const float* W_ih = (const float*)d_in[4];
    const float* W_hh = (const float*)d_in[5];
    const float* b_ih = (const float*)d_in[6];
    const float* b_hh = (const float*)d_in[7];
    float* out = (float*)d_out;
    (void)in_sizes; (void)n_in; (void)out_size;

    cudaFuncSetAttribute(prep_ux_kernel, cudaFuncAttributeMaxDynamicSharedMemorySize, 131072);
    cudaFuncSetAttribute(main_kernel,    cudaFuncAttributeMaxDynamicSharedMemorySize, SMEM_MAIN);

    prep_w_kernel<<<256, 256>>>(W_ih, W_hh, b_ih, b_hh, We);
    prep_ux_kernel<<<BATCH, 256, 131072>>>(x, Ue);
    main_kernel<<<CTAS, THREADS, SMEM_MAIN>>>(x, v_e, out);
}